// round 4
// baseline (speedup 1.0000x reference)
#include <cuda_runtime.h>
#include <cuda_bf16.h>
#include <math.h>
#include <stdint.h>

#define BATCH 4
#define SEQ   2048
#define HID   256
#define NTOK  (BATCH*SEQ)   // 8192
#define NHEAD 8
#define DPH   32
#define WINSZ 64
#define NWIN  32

typedef __nv_bfloat16 bf16;

// ---------------- scratch (no allocs allowed) ----------------
__device__ float g_q[NTOK*HID];
__device__ float g_k[NTOK*HID];
__device__ float g_v[NTOK*HID];
__device__ float g_pe[NTOK*HID];

__device__ bf16 g_ah[NTOK*HID],   g_al[NTOK*HID];     // inputs split
__device__ bf16 g_pe1h[NTOK*HID], g_pe1l[NTOK*HID];   // pos-mlp stage1 split
__device__ bf16 g_ctxh[NTOK*HID], g_ctxl[NTOK*HID];   // attn output split
__device__ bf16 g_wh[5*HID*HID],  g_wl[5*HID*HID];    // 5 weights split

__device__ float g_cw0[HID], g_cw1[HID], g_cb1[HID];  // centered pos1 weights
__device__ float g_pstat[6];                          // Saa,Sbb,Sab,Sac,Sbc,Scc

__device__ __forceinline__ float gelu_exact(float x) {
    return 0.5f * x * (1.0f + erff(x * 0.70710678118654752f));
}

__device__ __forceinline__ uint32_t pkbf(float a, float b) {
    bf16 ha = __float2bfloat16(a);
    bf16 hb = __float2bfloat16(b);
    return (uint32_t)__bfloat16_as_ushort(ha) |
           ((uint32_t)__bfloat16_as_ushort(hb) << 16);
}
__device__ __forceinline__ float bfv(uint32_t p, int hi) {
    return __bfloat162float(__ushort_as_bfloat16((unsigned short)(hi ? (p >> 16) : p)));
}

__device__ __forceinline__ void ldsm4(uint32_t* r, const void* p) {
    uint32_t a = (uint32_t)__cvta_generic_to_shared(p);
    asm volatile("ldmatrix.sync.aligned.m8n8.x4.shared.b16 {%0,%1,%2,%3}, [%4];"
                 : "=r"(r[0]), "=r"(r[1]), "=r"(r[2]), "=r"(r[3]) : "r"(a));
}
__device__ __forceinline__ void ldsm4t(uint32_t* r, const void* p) {
    uint32_t a = (uint32_t)__cvta_generic_to_shared(p);
    asm volatile("ldmatrix.sync.aligned.m8n8.x4.trans.shared.b16 {%0,%1,%2,%3}, [%4];"
                 : "=r"(r[0]), "=r"(r[1]), "=r"(r[2]), "=r"(r[3]) : "r"(a));
}
__device__ __forceinline__ void mma_bf16(float* d, const uint32_t* a, const uint32_t* b) {
    asm volatile(
        "mma.sync.aligned.m16n8k16.row.col.f32.bf16.bf16.f32 "
        "{%0,%1,%2,%3}, {%4,%5,%6,%7}, {%8,%9}, {%0,%1,%2,%3};\n"
        : "+f"(d[0]), "+f"(d[1]), "+f"(d[2]), "+f"(d[3])
        : "r"(a[0]), "r"(a[1]), "r"(a[2]), "r"(a[3]), "r"(b[0]), "r"(b[1]));
}

// ---------------- prep: split 5 weights to bf16 hi/lo ----------------
__global__ __launch_bounds__(256) void prep_w(
    const float* __restrict__ wq, const float* __restrict__ wk,
    const float* __restrict__ wv, const float* __restrict__ p2w,
    const float* __restrict__ wo)
{
    const int w = blockIdx.x;
    const float* src = (w == 0) ? wq : (w == 1) ? wk : (w == 2) ? wv :
                       (w == 3) ? p2w : wo;
    const int base = blockIdx.y * 4096 + threadIdx.x * 16;
#pragma unroll
    for (int i = 0; i < 4; i++) {
        int idx = base + i * 4;
        float4 v = *(const float4*)(src + idx);
        int o = w * 65536 + idx;
        float hx = bfv(pkbf(v.x, v.y), 0), hy = bfv(pkbf(v.x, v.y), 1);
        float hz = bfv(pkbf(v.z, v.w), 0), hw = bfv(pkbf(v.z, v.w), 1);
        *(uint32_t*)(&g_wh[o])     = pkbf(v.x, v.y);
        *(uint32_t*)(&g_wh[o + 2]) = pkbf(v.z, v.w);
        *(uint32_t*)(&g_wl[o])     = pkbf(v.x - hx, v.y - hy);
        *(uint32_t*)(&g_wl[o + 2]) = pkbf(v.z - hz, v.w - hw);
    }
}

// ---------------- prep: split inputs to bf16 hi/lo ----------------
__global__ __launch_bounds__(256) void prep_a(const float* __restrict__ A)
{
    const int idx = (blockIdx.x * 256 + threadIdx.x) * 4;
    float4 v = *(const float4*)(A + idx);
    uint32_t h01 = pkbf(v.x, v.y), h23 = pkbf(v.z, v.w);
    *(uint32_t*)(&g_ah[idx])     = h01;
    *(uint32_t*)(&g_ah[idx + 2]) = h23;
    *(uint32_t*)(&g_al[idx]) = pkbf(v.x - bfv(h01,0), v.y - bfv(h01,1));
    *(uint32_t*)(&g_al[idx + 2]) = pkbf(v.z - bfv(h23,0), v.w - bfv(h23,1));
}

// ---------------- prep: pos1 statistics (one block) ----------------
__global__ __launch_bounds__(256) void pstat_k(
    const float* __restrict__ p1w, const float* __restrict__ p1b)
{
    __shared__ float red[8];
    const int t = threadIdx.x;
    const int lane = t & 31, warp = t >> 5;
    float w0 = p1w[t], w1 = p1w[256 + t], b0 = p1b[t];

    float sums[3] = {w0, w1, b0};
    float means[3];
#pragma unroll
    for (int s = 0; s < 3; s++) {
        float v = sums[s];
#pragma unroll
        for (int o = 16; o; o >>= 1) v += __shfl_xor_sync(0xffffffffu, v, o);
        if (lane == 0) red[warp] = v;
        __syncthreads();
        float tot = 0.f;
#pragma unroll
        for (int i = 0; i < 8; i++) tot += red[i];
        means[s] = tot * (1.f / 256.f);
        __syncthreads();
    }
    float a = w0 - means[0], b = w1 - means[1], c = b0 - means[2];
    g_cw0[t] = a; g_cw1[t] = b; g_cb1[t] = c;

    float prods[6] = {a*a, b*b, a*b, a*c, b*c, c*c};
#pragma unroll
    for (int s = 0; s < 6; s++) {
        float v = prods[s];
#pragma unroll
        for (int o = 16; o; o >>= 1) v += __shfl_xor_sync(0xffffffffu, v, o);
        if (lane == 0) red[warp] = v;
        __syncthreads();
        if (t == 0) {
            float tot = 0.f;
#pragma unroll
            for (int i = 0; i < 8; i++) tot += red[i];
            g_pstat[s] = tot * (1.f / 256.f);
        }
        __syncthreads();
    }
}

// ---------------- pos1: reduction-free, writes bf16 split ----------------
__global__ __launch_bounds__(256) void pos1_k(
    const float* __restrict__ p, const float* __restrict__ lng,
    const float* __restrict__ lnb)
{
    const int warp = threadIdx.x >> 5;
    const int lane = threadIdx.x & 31;
    const int tok = blockIdx.x * 8 + warp;
    const float p0 = p[tok * 2 + 0];
    const float p1 = p[tok * 2 + 1];
    const float var = p0*p0*g_pstat[0] + p1*p1*g_pstat[1] + 2.f*p0*p1*g_pstat[2]
                    + 2.f*p0*g_pstat[3] + 2.f*p1*g_pstat[4] + g_pstat[5];
    const float rstd = rsqrtf(var + 1e-6f);

    const int n0 = lane * 8;
    float y[8];
#pragma unroll
    for (int i = 0; i < 8; i += 4) {
        float4 a4 = *(const float4*)(g_cw0 + n0 + i);
        float4 b4 = *(const float4*)(g_cw1 + n0 + i);
        float4 c4 = *(const float4*)(g_cb1 + n0 + i);
        float4 gg = *(const float4*)(lng + n0 + i);
        float4 bb = *(const float4*)(lnb + n0 + i);
        y[i+0] = gelu_exact((p0*a4.x + p1*b4.x + c4.x) * rstd * gg.x + bb.x);
        y[i+1] = gelu_exact((p0*a4.y + p1*b4.y + c4.y) * rstd * gg.y + bb.y);
        y[i+2] = gelu_exact((p0*a4.z + p1*b4.z + c4.z) * rstd * gg.z + bb.z);
        y[i+3] = gelu_exact((p0*a4.w + p1*b4.w + c4.w) * rstd * gg.w + bb.w);
    }
    const size_t o = (size_t)tok * 256 + n0;
    uint2 hh, ll;
    hh.x = pkbf(y[0], y[1]); hh.y = pkbf(y[2], y[3]);
    ll.x = pkbf(y[0]-bfv(hh.x,0), y[1]-bfv(hh.x,1));
    ll.y = pkbf(y[2]-bfv(hh.y,0), y[3]-bfv(hh.y,1));
    *(uint2*)(&g_pe1h[o]) = hh;
    *(uint2*)(&g_pe1l[o]) = ll;
    hh.x = pkbf(y[4], y[5]); hh.y = pkbf(y[6], y[7]);
    ll.x = pkbf(y[4]-bfv(hh.x,0), y[5]-bfv(hh.x,1));
    ll.y = pkbf(y[6]-bfv(hh.y,0), y[7]-bfv(hh.y,1));
    *(uint2*)(&g_pe1h[o + 4]) = hh;
    *(uint2*)(&g_pe1l[o + 4]) = ll;
}

// ---------------- GEMM core: pre-split bf16 operands, 3x compensated ----------------
#define BM 128
#define BN 64
#define BKG 32

__device__ __forceinline__ void gemm_core(
    const bf16* __restrict__ Ahg, const bf16* __restrict__ Alg,
    const bf16* __restrict__ Whg, const bf16* __restrict__ Wlg,
    const float* __restrict__ bias, float* __restrict__ C,
    float scale, int act, int bx, int by)
{
    __shared__ bf16 sAh[BM][40];
    __shared__ bf16 sAl[BM][40];
    __shared__ bf16 sBh[BKG][72];
    __shared__ bf16 sBl[BKG][72];

    const int tid  = threadIdx.x;
    const int wid  = tid >> 5;
    const int lane = tid & 31;
    const int g = lane >> 2;
    const int q = lane & 3;
    const int wm = (wid & 3) * 32;
    const int wn = (wid >> 2) * 32;
    const int m0 = bx * BM;
    const int n0 = by * BN;

    float acc[2][4][4];
#pragma unroll
    for (int mt = 0; mt < 2; mt++)
#pragma unroll
        for (int nt = 0; nt < 4; nt++)
#pragma unroll
            for (int i = 0; i < 4; i++) acc[mt][nt][i] = 0.f;

    uint4 rah[2], ral[2], rbh, rbl;
    const int arow = tid >> 2, acol = (tid & 3) * 8;      // A: 4 chunks/row
    const int brow = tid >> 3, bcol = (tid & 7) * 8;      // B: 8 chunks/row

#define LOADG(KK)                                                              \
    {                                                                          \
        rah[0] = *(const uint4*)(Ahg + (size_t)(m0 + arow) * 256 + (KK) + acol);      \
        rah[1] = *(const uint4*)(Ahg + (size_t)(m0 + arow + 64) * 256 + (KK) + acol); \
        ral[0] = *(const uint4*)(Alg + (size_t)(m0 + arow) * 256 + (KK) + acol);      \
        ral[1] = *(const uint4*)(Alg + (size_t)(m0 + arow + 64) * 256 + (KK) + acol); \
        rbh = *(const uint4*)(Whg + (size_t)((KK) + brow) * 256 + n0 + bcol);  \
        rbl = *(const uint4*)(Wlg + (size_t)((KK) + brow) * 256 + n0 + bcol);  \
    }
#define STAGE()                                                                \
    {                                                                          \
        *(uint4*)(&sAh[arow][acol])      = rah[0];                             \
        *(uint4*)(&sAh[arow + 64][acol]) = rah[1];                             \
        *(uint4*)(&sAl[arow][acol])      = ral[0];                             \
        *(uint4*)(&sAl[arow + 64][acol]) = ral[1];                             \
        *(uint4*)(&sBh[brow][bcol])      = rbh;                                \
        *(uint4*)(&sBl[brow][bcol])      = rbl;                                \
    }

    LOADG(0);
    const int la = lane & 15;
    const int lo8 = (lane >> 4) << 3;
    for (int kk = 0; kk < 256; kk += BKG) {
        STAGE();
        __syncthreads();
        if (kk + BKG < 256) LOADG(kk + BKG);

#pragma unroll
        for (int ks = 0; ks < BKG; ks += 16) {
            uint32_t ah[2][4], al[2][4], bh[2][4], bl[2][4];
#pragma unroll
            for (int mt = 0; mt < 2; mt++) {
                ldsm4(ah[mt], &sAh[wm + mt * 16 + la][ks + lo8]);
                ldsm4(al[mt], &sAl[wm + mt * 16 + la][ks + lo8]);
            }
#pragma unroll
            for (int np = 0; np < 2; np++) {
                ldsm4t(bh[np], &sBh[ks + la][wn + np * 16 + lo8]);
                ldsm4t(bl[np], &sBl[ks + la][wn + np * 16 + lo8]);
            }
#pragma unroll
            for (int mt = 0; mt < 2; mt++)
#pragma unroll
                for (int nt = 0; nt < 4; nt++) {
                    const uint32_t* ph = &bh[nt >> 1][(nt & 1) * 2];
                    const uint32_t* pl = &bl[nt >> 1][(nt & 1) * 2];
                    mma_bf16(acc[mt][nt], ah[mt], ph);
                    mma_bf16(acc[mt][nt], ah[mt], pl);
                    mma_bf16(acc[mt][nt], al[mt], ph);
                }
        }
        __syncthreads();
    }

#pragma unroll
    for (int mt = 0; mt < 2; mt++) {
        int r0 = m0 + wm + mt * 16 + g;
#pragma unroll
        for (int nt = 0; nt < 4; nt++) {
            int cn = n0 + wn + nt * 8 + 2 * q;
            float2 b2 = *(const float2*)(bias + cn);
            float v0 = (acc[mt][nt][0] + b2.x) * scale;
            float v1 = (acc[mt][nt][1] + b2.y) * scale;
            float v2 = (acc[mt][nt][2] + b2.x) * scale;
            float v3 = (acc[mt][nt][3] + b2.y) * scale;
            if (act) {
                v0 = gelu_exact(v0); v1 = gelu_exact(v1);
                v2 = gelu_exact(v2); v3 = gelu_exact(v3);
            }
            *(float2*)(C + (size_t)r0 * 256 + cn)       = make_float2(v0, v1);
            *(float2*)(C + (size_t)(r0 + 8) * 256 + cn) = make_float2(v2, v3);
        }
    }
#undef LOADG
#undef STAGE
}

// fused QKV: blockIdx.z selects weight/output
__global__ __launch_bounds__(256) void gemm_qkv(
    const float* __restrict__ bq, const float* __restrict__ bk,
    const float* __restrict__ bv)
{
    const int z = blockIdx.z;
    const float* bias = (z == 0) ? bq : (z == 1) ? bk : bv;
    float* C = (z == 0) ? g_q : (z == 1) ? g_k : g_v;
    float scale = (z == 0) ? 0.17677669529663689f : 1.f;
    gemm_core(g_ah, g_al, g_wh + (size_t)z * 65536, g_wl + (size_t)z * 65536,
              bias, C, scale, 0, blockIdx.x, blockIdx.y);
}

__global__ __launch_bounds__(256) void gemm_pe(const float* __restrict__ p2b)
{
    gemm_core(g_pe1h, g_pe1l, g_wh + (size_t)3 * 65536, g_wl + (size_t)3 * 65536,
              p2b, g_pe, 1.f, 1, blockIdx.x, blockIdx.y);
}

__global__ __launch_bounds__(256) void gemm_out(const float* __restrict__ bo,
                                                float* __restrict__ out)
{
    gemm_core(g_ctxh, g_ctxl, g_wh + (size_t)4 * 65536, g_wl + (size_t)4 * 65536,
              bo, out, 1.f, 0, blockIdx.x, blockIdx.y);
}

// ---------------- windowed attention ----------------
// S[i,j] = q_i·(k_j - pe_j) + (c·k_j - d·pe_j) + (q_i + d)·pe_i
__global__ __launch_bounds__(256) void attn_k(
    const float* __restrict__ cvec, const float* __restrict__ dvec)
{
    const int w = blockIdx.x, h = blockIdx.y, b = blockIdx.z;

    __shared__ float sq[64][36];
    __shared__ float skw[64][36];
    __shared__ float sv[64][36];
    __shared__ float sbias[64];
    __shared__ float su[64];
    __shared__ float P[64][65];

    const int t = threadIdx.x;
    const int tok = t >> 2;
    const int l = t & 3;
    const int dl = l * 8;

    const int s = w * 64 + tok;
    const int o = s >> 4, r = s & 15;
    const int ic = ((o & 63) << 1) + (o >> 6);
    const int orig = ic * 16 + r;
    const size_t base = ((size_t)(b * SEQ + orig)) * 256 + h * 32 + dl;

    const float* cp = cvec + h * 32 + dl;
    const float* dp = dvec + h * 32 + dl;

    float bias_p = 0.f, u_p = 0.f;
#pragma unroll
    for (int i = 0; i < 8; i += 4) {
        float4 xq = *(const float4*)(g_q + base + i);
        float4 xk = *(const float4*)(g_k + base + i);
        float4 xv = *(const float4*)(g_v + base + i);
        float4 xp = *(const float4*)(g_pe + base + i);
        float4 xc = *(const float4*)(cp + i);
        float4 xd = *(const float4*)(dp + i);
        *(float4*)(&sq[tok][dl + i]) = xq;
        *(float4*)(&sv[tok][dl + i]) = xv;
        float4 kw = make_float4(xk.x - xp.x, xk.y - xp.y, xk.z - xp.z, xk.w - xp.w);
        *(float4*)(&skw[tok][dl + i]) = kw;
        bias_p += xc.x * xk.x + xc.y * xk.y + xc.z * xk.z + xc.w * xk.w;
        bias_p -= xd.x * xp.x + xd.y * xp.y + xd.z * xp.z + xd.w * xp.w;
        u_p += (xq.x + xd.x) * xp.x + (xq.y + xd.y) * xp.y +
               (xq.z + xd.z) * xp.z + (xq.w + xd.w) * xp.w;
    }
    bias_p += __shfl_xor_sync(0xffffffffu, bias_p, 1);
    bias_p += __shfl_xor_sync(0xffffffffu, bias_p, 2);
    u_p += __shfl_xor_sync(0xffffffffu, u_p, 1);
    u_p += __shfl_xor_sync(0xffffffffu, u_p, 2);
    if (l == 0) { sbias[tok] = bias_p; su[tok] = u_p; }
    __syncthreads();

    const int row = tok;
    float qrow[32];
#pragma unroll
    for (int d = 0; d < 32; d += 4) {
        float4 x = *(const float4*)(&sq[row][d]);
        qrow[d] = x.x; qrow[d + 1] = x.y; qrow[d + 2] = x.z; qrow[d + 3] = x.w;
    }
    const float urow = su[row];
    float sc[16];
    float smax = -1e30f;
#pragma unroll
    for (int jj = 0; jj < 16; jj++) {
        int j = l + (jj << 2);
        float sv2 = urow + sbias[j];
#pragma unroll
        for (int d = 0; d < 32; d += 4) {
            float4 kv = *(const float4*)(&skw[j][d]);
            sv2 += qrow[d] * kv.x + qrow[d + 1] * kv.y +
                   qrow[d + 2] * kv.z + qrow[d + 3] * kv.w;
        }
        sc[jj] = sv2;
        smax = fmaxf(smax, sv2);
    }
    smax = fmaxf(smax, __shfl_xor_sync(0xffffffffu, smax, 1));
    smax = fmaxf(smax, __shfl_xor_sync(0xffffffffu, smax, 2));
    float ssum = 0.f;
#pragma unroll
    for (int jj = 0; jj < 16; jj++) {
        sc[jj] = __expf(sc[jj] - smax);
        ssum += sc[jj];
    }
    ssum += __shfl_xor_sync(0xffffffffu, ssum, 1);
    ssum += __shfl_xor_sync(0xffffffffu, ssum, 2);
    const float inv = 1.f / ssum;
#pragma unroll
    for (int jj = 0; jj < 16; jj++) P[row][l + (jj << 2)] = sc[jj] * inv;
    __syncthreads();

    float oa[8];
#pragma unroll
    for (int i = 0; i < 8; i++) oa[i] = 0.f;
#pragma unroll
    for (int j = 0; j < 64; j++) {
        float pv = P[row][j];
        float4 v0 = *(const float4*)(&sv[j][dl]);
        float4 v1 = *(const float4*)(&sv[j][dl + 4]);
        oa[0] += pv * v0.x; oa[1] += pv * v0.y; oa[2] += pv * v0.z; oa[3] += pv * v0.w;
        oa[4] += pv * v1.x; oa[5] += pv * v1.y; oa[6] += pv * v1.z; oa[7] += pv * v1.w;
    }
    // write ctx as bf16 hi/lo split (feeds output GEMM directly)
    uint2 hh, ll;
    hh.x = pkbf(oa[0], oa[1]); hh.y = pkbf(oa[2], oa[3]);
    ll.x = pkbf(oa[0]-bfv(hh.x,0), oa[1]-bfv(hh.x,1));
    ll.y = pkbf(oa[2]-bfv(hh.y,0), oa[3]-bfv(hh.y,1));
    *(uint2*)(&g_ctxh[base]) = hh;
    *(uint2*)(&g_ctxl[base]) = ll;
    hh.x = pkbf(oa[4], oa[5]); hh.y = pkbf(oa[6], oa[7]);
    ll.x = pkbf(oa[4]-bfv(hh.x,0), oa[5]-bfv(hh.x,1));
    ll.y = pkbf(oa[6]-bfv(hh.y,0), oa[7]-bfv(hh.y,1));
    *(uint2*)(&g_ctxh[base + 4]) = hh;
    *(uint2*)(&g_ctxl[base + 4]) = ll;
}

// ---------------- launch ----------------
extern "C" void kernel_launch(void* const* d_in, const int* in_sizes, int n_in,
                              void* d_out, int out_size)
{
    const float* inputs = (const float*)d_in[0];
    const float* p      = (const float*)d_in[1];
    const float* wq     = (const float*)d_in[2];
    const float* bq     = (const float*)d_in[3];
    const float* wk     = (const float*)d_in[4];
    const float* bk     = (const float*)d_in[5];
    const float* wv     = (const float*)d_in[6];
    const float* bv     = (const float*)d_in[7];
    const float* wo     = (const float*)d_in[8];
    const float* bo     = (const float*)d_in[9];
    const float* p1w    = (const float*)d_in[10];
    const float* p1b    = (const float*)d_in[11];
    const float* p2w    = (const float*)d_in[12];
    const float* p2b    = (const float*)d_in[13];
    const float* lng    = (const float*)d_in[14];
    const float* lnb    = (const float*)d_in[15];
    const float* cv     = (const float*)d_in[16];
    const float* dv     = (const float*)d_in[17];
    float* out = (float*)d_out;

    const dim3 gg(NTOK / BM, HID / BN, 1);

    prep_w<<<dim3(5, 16), 256>>>(wq, wk, wv, p2w, wo);
    prep_a<<<NTOK * HID / 1024, 256>>>(inputs);
    pstat_k<<<1, 256>>>(p1w, p1b);
    pos1_k<<<NTOK / 8, 256>>>(p, lng, lnb);
    gemm_qkv<<<dim3(NTOK / BM, HID / BN, 3), 256>>>(bq, bk, bv);
    gemm_pe<<<gg, 256>>>(p2b);
    attn_k<<<dim3(NWIN, NHEAD, BATCH), 256>>>(cv, dv);
    gemm_out<<<gg, 256>>>(bo, out);
}